// round 13
// baseline (speedup 1.0000x reference)
#include <cuda_runtime.h>
#include <cuda_bf16.h>
#include <math.h>
#include <stdint.h>

#define N_TOK 8192
#define DIMH  256
#define NOUT  513
#define SEGL  1024
#define NSEG  8
#define EPAIR 65536
#define COND_GRID 1024

// ---------------- scratch (static device memory; no allocations) ----------------
__device__ float  g_QKL[N_TOK * NOUT];
__device__ __nv_bfloat16 g_Qh[N_TOK * DIMH];
__device__ __nv_bfloat16 g_Kh[N_TOK * DIMH];
__device__ float  g_logit[N_TOK];
__device__ float  g_Wall[N_TOK];
__device__ float  g_logZ[N_TOK];
__device__ float  g_partM[NSEG * 8 * 8 * 128];   // (seg, rb, chunk, row); untouched slots stay 0
__device__ float  g_partL[NSEG * 8 * 8 * 128];
__device__ float  g_z[NSEG];
__device__ double g_accCond;
__device__ unsigned int g_ctr;                   // self-resetting via atomicInc wrap

// 36 jobs per segment: rowblock rb (128 rows) x keyblock ch (128 cols), ch <= rb
__constant__ unsigned char JOB_RB[36] = {
    0, 1,1, 2,2,2, 3,3,3,3, 4,4,4,4,4, 5,5,5,5,5,5,
    6,6,6,6,6,6,6, 7,7,7,7,7,7,7,7};
__constant__ unsigned char JOB_CH[36] = {
    0, 0,1, 0,1,2, 0,1,2,3, 0,1,2,3,4, 0,1,2,3,4,5,
    0,1,2,3,4,5,6, 0,1,2,3,4,5,6,7};

// ---------------- helpers ----------------
__device__ __forceinline__ void mma_bf16(float* c, uint32_t a0, uint32_t a1,
                                         uint32_t a2, uint32_t a3,
                                         uint32_t b0, uint32_t b1) {
    asm("mma.sync.aligned.m16n8k16.row.col.f32.bf16.bf16.f32 "
        "{%0,%1,%2,%3},{%4,%5,%6,%7},{%8,%9},{%0,%1,%2,%3};"
        : "+f"(c[0]), "+f"(c[1]), "+f"(c[2]), "+f"(c[3])
        : "r"(a0), "r"(a1), "r"(a2), "r"(a3), "r"(b0), "r"(b1));
}
__device__ __forceinline__ void ldmat4(uint32_t& r0, uint32_t& r1,
                                       uint32_t& r2, uint32_t& r3, uint32_t addr) {
    asm volatile("ldmatrix.sync.aligned.m8n8.x4.shared.b16 {%0,%1,%2,%3}, [%4];"
                 : "=r"(r0), "=r"(r1), "=r"(r2), "=r"(r3) : "r"(addr));
}
__device__ __forceinline__ uint32_t packbf2(float lo, float hi) {
    __nv_bfloat162 h = __floats2bfloat162_rn(lo, hi);
    return *(uint32_t*)&h;
}

// ---------------- kernel A: projection GEMM (bf16 mma + ldmatrix + reg prefetch) ----------------
__global__ void __launch_bounds__(256) proj_bf16(const float* __restrict__ A,
                                                 const float* __restrict__ W,
                                                 const float* __restrict__ bias) {
    const int tid = threadIdx.x;
    const int m0 = blockIdx.y * 128;

    if (blockIdx.x == 4) {
        int gz = blockIdx.y * 256 + tid;
        if (gz < N_TOK) g_Wall[gz] = 0.f;
        if (blockIdx.y == 0 && tid == 0) g_accCond = 0.0;
        const int warp = tid >> 5, lane = tid & 31;
        const float* wr = &W[512 * DIMH + lane * 8];
        float4 w0 = *(const float4*)wr;
        float4 w1 = *(const float4*)(wr + 4);
        float b512 = bias[512];
        for (int t = 0; t < 16; t++) {
            int row = m0 + warp * 16 + t;
            const float* ar = &A[row * DIMH + lane * 8];
            float4 a0 = *(const float4*)ar;
            float4 a1 = *(const float4*)(ar + 4);
            float d = a0.x * w0.x + a0.y * w0.y + a0.z * w0.z + a0.w * w0.w
                    + a1.x * w1.x + a1.y * w1.y + a1.z * w1.z + a1.w * w1.w;
#pragma unroll
            for (int o = 16; o; o >>= 1) d += __shfl_xor_sync(0xffffffffu, d, o);
            if (lane == 0) g_QKL[row * NOUT + 512] = d + b512;
        }
        return;
    }

    __shared__ uint32_t As[128][20];
    __shared__ uint32_t Bs[128][20];
    const int n0 = blockIdx.x * 128;
    const int wid = tid >> 5, lane = tid & 31;
    const int g = lane >> 2, tig = lane & 3;

    uint32_t asm_ = (uint32_t)__cvta_generic_to_shared(&As[0][0]);
    uint32_t bsm = (uint32_t)__cvta_generic_to_shared(&Bs[0][0]);
    const uint32_t aBase = asm_ + (((wid * 16 + (lane & 15)) * 20 + ((lane >> 4) << 2)) << 2);
    const uint32_t bBase = bsm + ((((((lane >> 4) << 3) + (lane & 7)) * 20
                                   + (((lane >> 3) & 1) << 2)) << 2));

    const int lr = tid >> 2, lj = tid & 3;

    float acc[16][4];
#pragma unroll
    for (int nt = 0; nt < 16; nt++)
#pragma unroll
        for (int e = 0; e < 4; e++) acc[nt][e] = 0.f;

    float4 pa[2][2], pb[2][2];
#pragma unroll
    for (int i = 0; i < 2; i++) {
        int r = lr + i * 64, gk = lj * 8;
        pa[i][0] = *(const float4*)&A[(m0 + r) * DIMH + gk];
        pa[i][1] = *(const float4*)&A[(m0 + r) * DIMH + gk + 4];
        pb[i][0] = *(const float4*)&W[(n0 + r) * DIMH + gk];
        pb[i][1] = *(const float4*)&W[(n0 + r) * DIMH + gk + 4];
    }

    for (int kc = 0; kc < 8; kc++) {
#pragma unroll
        for (int i = 0; i < 2; i++) {
            int r = lr + i * 64;
            uint4 apk = make_uint4(packbf2(pa[i][0].x, pa[i][0].y), packbf2(pa[i][0].z, pa[i][0].w),
                                   packbf2(pa[i][1].x, pa[i][1].y), packbf2(pa[i][1].z, pa[i][1].w));
            uint4 bpk = make_uint4(packbf2(pb[i][0].x, pb[i][0].y), packbf2(pb[i][0].z, pb[i][0].w),
                                   packbf2(pb[i][1].x, pb[i][1].y), packbf2(pb[i][1].z, pb[i][1].w));
            *(uint4*)&As[r][lj * 4] = apk;
            *(uint4*)&Bs[r][lj * 4] = bpk;
        }
        __syncthreads();
        if (kc < 7) {
            int gk = (kc + 1) * 32 + lj * 8;
#pragma unroll
            for (int i = 0; i < 2; i++) {
                int r = lr + i * 64;
                pa[i][0] = *(const float4*)&A[(m0 + r) * DIMH + gk];
                pa[i][1] = *(const float4*)&A[(m0 + r) * DIMH + gk + 4];
                pb[i][0] = *(const float4*)&W[(n0 + r) * DIMH + gk];
                pb[i][1] = *(const float4*)&W[(n0 + r) * DIMH + gk + 4];
            }
        }
#pragma unroll
        for (int s = 0; s < 2; s++) {
            uint32_t a0, a1, a2, a3;
            ldmat4(a0, a1, a2, a3, aBase + s * 32);
#pragma unroll
            for (int nt2 = 0; nt2 < 8; nt2++) {
                uint32_t b0, b1, b2, b3;
                ldmat4(b0, b1, b2, b3, bBase + nt2 * 1280 + s * 32);
                mma_bf16(acc[2 * nt2], a0, a1, a2, a3, b0, b1);
                mma_bf16(acc[2 * nt2 + 1], a0, a1, a2, a3, b2, b3);
            }
        }
        __syncthreads();
    }

    const int r0 = m0 + wid * 16 + g;
#pragma unroll
    for (int nt = 0; nt < 16; nt++) {
        int c0 = n0 + nt * 8 + tig * 2;
        float bv0 = bias[c0], bv1 = bias[c0 + 1];
        g_QKL[r0 * NOUT + c0] = acc[nt][0] + bv0;
        g_QKL[r0 * NOUT + c0 + 1] = acc[nt][1] + bv1;
        g_QKL[(r0 + 8) * NOUT + c0] = acc[nt][2] + bv0;
        g_QKL[(r0 + 8) * NOUT + c0 + 1] = acc[nt][3] + bv1;
    }
}

// ---------------- kernel B: warp-per-row layernorm (bf16 outputs only) ----------------
__global__ void __launch_bounds__(256) ln_warp(const float* __restrict__ lnw,
                                               const float* __restrict__ lnb) {
    const int row = blockIdx.x * 8 + (threadIdx.x >> 5);
    const int lane = threadIdx.x & 31;
    const float* x = &g_QKL[row * NOUT];

    float xv[16];
#pragma unroll
    for (int t = 0; t < 16; t++) xv[t] = x[lane + 32 * t];
    float x512 = x[512];

    float sum = (lane == 0) ? x512 : 0.f;
    float sq  = (lane == 0) ? x512 * x512 : 0.f;
#pragma unroll
    for (int t = 0; t < 16; t++) { sum += xv[t]; sq += xv[t] * xv[t]; }
#pragma unroll
    for (int o = 16; o; o >>= 1) {
        sum += __shfl_xor_sync(0xffffffffu, sum, o);
        sq  += __shfl_xor_sync(0xffffffffu, sq, o);
    }
    float mean = sum * (1.f / 513.f);
    float var  = sq * (1.f / 513.f) - mean * mean;
    float rstd = rsqrtf(var + 1e-5f);

#pragma unroll
    for (int t = 0; t < 8; t++) {
        int c = lane + 32 * t;
        float qv = (xv[t] - mean) * rstd * lnw[c] + lnb[c];
        g_Qh[row * DIMH + c] = __float2bfloat16_rn(qv);
    }
#pragma unroll
    for (int t = 0; t < 8; t++) {
        int c = lane + 32 * t;
        float kv = (xv[t + 8] - mean) * rstd * lnw[256 + c] + lnb[256 + c];
        g_Kh[row * DIMH + c] = __float2bfloat16_rn(kv);
    }
    if (lane == 0)
        g_logit[row] = (x512 - mean) * rstd * lnw[512] + lnb[512];
}

// ---------------- kernel D: causal attention partial LSE (bf16 + ldmatrix + prefetch) ----------------
__global__ void __launch_bounds__(256) attn_bf16() {
    int bx = blockIdx.x;
    int seg = bx / 36;
    int jid = bx - seg * 36;
    int rb = JOB_RB[jid];
    int ch = JOB_CH[jid];

    __shared__ uint32_t Qp[128][20];
    __shared__ uint32_t Kp[128][20];
    const int tid = threadIdx.x;
    const int wid = tid >> 5, lane = tid & 31;
    const int g = lane >> 2, tig = lane & 3;
    const int base = seg * SEGL;

    const uint32_t* Qg = (const uint32_t*)&g_Qh[0];
    const uint32_t* Kg = (const uint32_t*)&g_Kh[0];

    uint32_t qsm = (uint32_t)__cvta_generic_to_shared(&Qp[0][0]);
    uint32_t ksm = (uint32_t)__cvta_generic_to_shared(&Kp[0][0]);
    const uint32_t aBase = qsm + (((wid * 16 + (lane & 15)) * 20 + ((lane >> 4) << 2)) << 2);
    const uint32_t bBase = ksm + ((((((lane >> 4) << 3) + (lane & 7)) * 20
                                   + (((lane >> 3) & 1) << 2)) << 2));

    const int lr = tid >> 2, lj = tid & 3;

    float acc[16][4];
#pragma unroll
    for (int nt = 0; nt < 16; nt++)
#pragma unroll
        for (int e = 0; e < 4; e++) acc[nt][e] = 0.f;

    uint4 pq[2], pk[2];
#pragma unroll
    for (int i = 0; i < 2; i++) {
        int r = lr + i * 64;
        pq[i] = *(const uint4*)&Qg[(base + rb * 128 + r) * 128 + lj * 4];
        pk[i] = *(const uint4*)&Kg[(base + ch * 128 + r) * 128 + lj * 4];
    }

    for (int kc = 0; kc < 8; kc++) {
#pragma unroll
        for (int i = 0; i < 2; i++) {
            int r = lr + i * 64;
            *(uint4*)&Qp[r][lj * 4] = pq[i];
            *(uint4*)&Kp[r][lj * 4] = pk[i];
        }
        __syncthreads();
        if (kc < 7) {
            int gk = (kc + 1) * 16 + lj * 4;
#pragma unroll
            for (int i = 0; i < 2; i++) {
                int r = lr + i * 64;
                pq[i] = *(const uint4*)&Qg[(base + rb * 128 + r) * 128 + gk];
                pk[i] = *(const uint4*)&Kg[(base + ch * 128 + r) * 128 + gk];
            }
        }
#pragma unroll
        for (int s = 0; s < 2; s++) {
            uint32_t a0, a1, a2, a3;
            ldmat4(a0, a1, a2, a3, aBase + s * 32);
#pragma unroll
            for (int nt2 = 0; nt2 < 8; nt2++) {
                uint32_t b0, b1, b2, b3;
                ldmat4(b0, b1, b2, b3, bBase + nt2 * 1280 + s * 32);
                mma_bf16(acc[2 * nt2], a0, a1, a2, a3, b0, b1);
                mma_bf16(acc[2 * nt2 + 1], a0, a1, a2, a3, b2, b3);
            }
        }
        __syncthreads();
    }

    const int pbase = ((seg * 8 + rb) * 8 + ch) * 128;
    const int rin0 = wid * 16 + g;
#pragma unroll
    for (int h = 0; h < 2; h++) {
        int rin = rin0 + h * 8;
        int irow = rb * 128 + rin;
        float mx = -INFINITY;
#pragma unroll
        for (int nt = 0; nt < 16; nt++) {
#pragma unroll
            for (int e = 0; e < 2; e++) {
                int jcol = ch * 128 + nt * 8 + tig * 2 + e;
                float v = acc[nt][h * 2 + e];
                if (jcol >= irow) v = -INFINITY;
                acc[nt][h * 2 + e] = v;
                mx = fmaxf(mx, v);
            }
        }
        mx = fmaxf(mx, __shfl_xor_sync(0xffffffffu, mx, 1));
        mx = fmaxf(mx, __shfl_xor_sync(0xffffffffu, mx, 2));
        float mb = fmaxf(mx, -3.0e38f);
        float s = 0.f;
#pragma unroll
        for (int nt = 0; nt < 16; nt++) {
            s += __expf(acc[nt][h * 2 + 0] - mb);
            s += __expf(acc[nt][h * 2 + 1] - mb);
        }
        s += __shfl_xor_sync(0xffffffffu, s, 1);
        s += __shfl_xor_sync(0xffffffffu, s, 2);
        if (tig == 0) {
            g_partM[pbase + rin] = mx;
            g_partL[pbase + rin] = s;
        }
    }
}

// ---------------- kernel E: combine/zseg pre-phase + cond sum + scatter + final ----------------
// cond phase: per-lane fp32 partials in 4 independent chains; 2 DADDs per lane total
__global__ void __launch_bounds__(256) cond_final(const float* __restrict__ wts,
                                                  const int* __restrict__ ii,
                                                  const int* __restrict__ jj,
                                                  float* __restrict__ out) {
    int tid = threadIdx.x;
    int bx = blockIdx.x;

    // --- pre-phase: logZ merge (blocks 0..31) and zseg (blocks 32..39) ---
    if (bx < 32) {
        int i = bx * 256 + tid;
        int seg = i >> 10;
        int r = i & 1023;
        int rb = r >> 7;
        int rr = r & 127;
        int pb = ((seg * 8 + rb) * 8) * 128 + rr;
        float m[8], l[8];
#pragma unroll
        for (int c = 0; c < 8; c++) {
            m[c] = g_partM[pb + c * 128];
            l[c] = g_partL[pb + c * 128];
        }
        float M = -INFINITY;
#pragma unroll
        for (int c = 0; c < 8; c++)
            M = fmaxf(M, (l[c] > 0.f) ? m[c] : -INFINITY);
        float Mb = fmaxf(M, -3.0e38f);
        float L = 0.f;
#pragma unroll
        for (int c = 0; c < 8; c++)
            L += l[c] * __expf(m[c] - Mb);
        g_logZ[i] = (L > 0.f) ? (M + logf(L)) : -INFINITY;
    } else if (bx < 40) {
        int seg = bx - 32;
        const float* lp = &g_logit[seg * SEGL];
        float vals[4];
        float mx = -INFINITY;
#pragma unroll
        for (int q = 0; q < 4; q++) { vals[q] = lp[tid + q * 256]; mx = fmaxf(mx, vals[q]); }
        __shared__ float shz[8];
#pragma unroll
        for (int o = 16; o; o >>= 1) mx = fmaxf(mx, __shfl_xor_sync(0xffffffffu, mx, o));
        if ((tid & 31) == 0) shz[tid >> 5] = mx;
        __syncthreads();
        float bm = -INFINITY;
#pragma unroll
        for (int i2 = 0; i2 < 8; i2++) bm = fmaxf(bm, shz[i2]);
        __syncthreads();
        float s = 0.f;
#pragma unroll
        for (int q = 0; q < 4; q++) s += expf(vals[q] - bm);
#pragma unroll
        for (int o = 16; o; o >>= 1) s += __shfl_xor_sync(0xffffffffu, s, o);
        if ((tid & 31) == 0) shz[tid >> 5] = s;
        __syncthreads();
        if (tid == 0) {
            float tot = 0.f;
#pragma unroll
            for (int i2 = 0; i2 < 8; i2++) tot += shz[i2];
            g_z[seg] = bm + logf(tot);
        }
        __syncthreads();
    }

    // --- cond gather + scatter (all blocks); fp32 partials, x4 unroll ---
    const int lane = tid & 31;
    const int warp = tid >> 5;
    const int gw = bx * 8 + warp;
    const int S = COND_GRID * 8;            // 8192 warps; 8 edges/warp; x4 unroll -> 2 iters
    const uint4* Qg = (const uint4*)&g_Qh[0];
    const uint4* Kg = (const uint4*)&g_Kh[0];
    double acc = 0.0;
    for (int e0 = gw; e0 < EPAIR; e0 += S * 4) {
        int iv[4], jv[4];
        float wv[4];
#pragma unroll
        for (int u = 0; u < 4; u++) {
            int e = e0 + u * S;
            iv[u] = ii[e];
            jv[u] = jj[e];
            wv[u] = wts[e];
        }
        uint4 qu[4], ku[4];
#pragma unroll
        for (int u = 0; u < 4; u++) {
            qu[u] = Qg[iv[u] * 32 + lane];
            ku[u] = Kg[jv[u] * 32 + lane];
        }
        float part[4];
#pragma unroll
        for (int u = 0; u < 4; u++) {
            const uint32_t* qw = (const uint32_t*)&qu[u];
            const uint32_t* kw = (const uint32_t*)&ku[u];
            float d = 0.f;
#pragma unroll
            for (int w = 0; w < 4; w++) {
                float2 qf = __bfloat1622float2(*(const __nv_bfloat162*)&qw[w]);
                float2 kf = __bfloat1622float2(*(const __nv_bfloat162*)&kw[w]);
                d += qf.x * kf.x + qf.y * kf.y;
            }
            part[u] = wv[u] * d;            // 4 independent fp32 chains
            if (lane == 0) atomicAdd(&g_Wall[iv[u]], wv[u]);
        }
        acc += (double)((part[0] + part[1]) + (part[2] + part[3]));  // 1 DADD per iter
    }
    __shared__ double shd[256];
    shd[tid] = acc;
    __syncthreads();
    for (int s = 128; s; s >>= 1) {
        if (tid < s) shd[tid] += shd[tid + s];
        __syncthreads();
    }
    __shared__ bool is_last;
    if (tid == 0) {
        atomicAdd(&g_accCond, shd[0]);
        __threadfence();
        unsigned old = atomicInc(&g_ctr, COND_GRID - 1);
        is_last = (old == COND_GRID - 1);
    }
    __syncthreads();
    if (is_last) {
        __threadfence();
        double facc = 0.0;
        for (int i = tid; i < N_TOK; i += 256) {
            float w = g_Wall[i];
            if (w > 0.f) {
                int seg = i >> 10;
                facc += (double)w * ((double)g_logit[i] - (double)g_z[seg] - (double)g_logZ[i]);
            }
        }
        __syncthreads();
        shd[tid] = facc;
        __syncthreads();
        for (int s = 128; s; s >>= 1) {
            if (tid < s) shd[tid] += shd[tid + s];
            __syncthreads();
        }
        if (tid == 0) {
            double cond = atomicAdd(&g_accCond, 0.0);
            out[0] = -(float)(cond + shd[0]);
        }
    }
}

// ---------------- launch ----------------
extern "C" void kernel_launch(void* const* d_in, const int* in_sizes, int n_in,
                              void* d_out, int out_size) {
    const float* hidden = (const float*)d_in[0];
    const float* Wp     = (const float*)d_in[1];
    const float* bp     = (const float*)d_in[2];
    const float* lnw    = (const float*)d_in[3];
    const float* lnb    = (const float*)d_in[4];
    const float* wts    = (const float*)d_in[5];
    const int*   ii     = (const int*)d_in[6];
    const int*   jj     = (const int*)d_in[7];
    float* out = (float*)d_out;

    proj_bf16<<<dim3(5, 64), 256>>>(hidden, Wp, bp);
    ln_warp<<<1024, 256>>>(lnw, lnb);
    attn_bf16<<<288, 256>>>();
    cond_final<<<COND_GRID, 256>>>(wts, ii, jj, out);
}

// round 14
// speedup vs baseline: 1.1039x; 1.1039x over previous
#include <cuda_runtime.h>
#include <cuda_bf16.h>
#include <math.h>
#include <stdint.h>

#define N_TOK 8192
#define DIMH  256
#define NOUT  513
#define SEGL  1024
#define NSEG  8
#define EPAIR 65536
#define COND_GRID 512

// ---------------- scratch (static device memory; no allocations) ----------------
__device__ __nv_bfloat16 g_QKLh[N_TOK * 512];    // proj output cols 0..511 (bf16)
__device__ float  g_logit512[N_TOK];             // proj output col 512 (fp32, exact)
__device__ __nv_bfloat16 g_Qh[N_TOK * DIMH];
__device__ __nv_bfloat16 g_Kh[N_TOK * DIMH];
__device__ float  g_logit[N_TOK];
__device__ float  g_Wall[N_TOK];
__device__ float  g_logZ[N_TOK];
__device__ float  g_partM[NSEG * 8 * 8 * 128];   // (seg, rb, chunk, row); untouched slots stay 0
__device__ float  g_partL[NSEG * 8 * 8 * 128];
__device__ float  g_z[NSEG];
__device__ double g_accCond;
__device__ unsigned int g_ctr;                   // self-resetting via atomicInc wrap

// 36 jobs per segment: rowblock rb (128 rows) x keyblock ch (128 cols), ch <= rb
__constant__ unsigned char JOB_RB[36] = {
    0, 1,1, 2,2,2, 3,3,3,3, 4,4,4,4,4, 5,5,5,5,5,5,
    6,6,6,6,6,6,6, 7,7,7,7,7,7,7,7};
__constant__ unsigned char JOB_CH[36] = {
    0, 0,1, 0,1,2, 0,1,2,3, 0,1,2,3,4, 0,1,2,3,4,5,
    0,1,2,3,4,5,6, 0,1,2,3,4,5,6,7};

// ---------------- helpers ----------------
__device__ __forceinline__ void mma_bf16(float* c, uint32_t a0, uint32_t a1,
                                         uint32_t a2, uint32_t a3,
                                         uint32_t b0, uint32_t b1) {
    asm("mma.sync.aligned.m16n8k16.row.col.f32.bf16.bf16.f32 "
        "{%0,%1,%2,%3},{%4,%5,%6,%7},{%8,%9},{%0,%1,%2,%3};"
        : "+f"(c[0]), "+f"(c[1]), "+f"(c[2]), "+f"(c[3])
        : "r"(a0), "r"(a1), "r"(a2), "r"(a3), "r"(b0), "r"(b1));
}
__device__ __forceinline__ void ldmat4(uint32_t& r0, uint32_t& r1,
                                       uint32_t& r2, uint32_t& r3, uint32_t addr) {
    asm volatile("ldmatrix.sync.aligned.m8n8.x4.shared.b16 {%0,%1,%2,%3}, [%4];"
                 : "=r"(r0), "=r"(r1), "=r"(r2), "=r"(r3) : "r"(addr));
}
__device__ __forceinline__ uint32_t packbf2(float lo, float hi) {
    __nv_bfloat162 h = __floats2bfloat162_rn(lo, hi);
    return *(uint32_t*)&h;
}
__device__ __forceinline__ float2 unpackbf2(uint32_t v) {
    return __bfloat1622float2(*(const __nv_bfloat162*)&v);
}

// ---------------- kernel A: projection GEMM (bf16 mma + ldmatrix + reg prefetch) ----------------
// bx 0..3: GEMM tile 128m x 128n -> bf16 output; bx == 4: zero duty + fp32 matvec for col 512
__global__ void __launch_bounds__(256) proj_bf16(const float* __restrict__ A,
                                                 const float* __restrict__ W,
                                                 const float* __restrict__ bias) {
    const int tid = threadIdx.x;
    const int m0 = blockIdx.y * 128;

    if (blockIdx.x == 4) {
        int gz = blockIdx.y * 256 + tid;
        if (gz < N_TOK) g_Wall[gz] = 0.f;
        if (blockIdx.y == 0 && tid == 0) g_accCond = 0.0;
        const int warp = tid >> 5, lane = tid & 31;
        const float* wr = &W[512 * DIMH + lane * 8];
        float4 w0 = *(const float4*)wr;
        float4 w1 = *(const float4*)(wr + 4);
        float b512 = bias[512];
        for (int t = 0; t < 16; t++) {
            int row = m0 + warp * 16 + t;
            const float* ar = &A[row * DIMH + lane * 8];
            float4 a0 = *(const float4*)ar;
            float4 a1 = *(const float4*)(ar + 4);
            float d = a0.x * w0.x + a0.y * w0.y + a0.z * w0.z + a0.w * w0.w
                    + a1.x * w1.x + a1.y * w1.y + a1.z * w1.z + a1.w * w1.w;
#pragma unroll
            for (int o = 16; o; o >>= 1) d += __shfl_xor_sync(0xffffffffu, d, o);
            if (lane == 0) g_logit512[row] = d + b512;
        }
        return;
    }

    __shared__ uint32_t As[128][20];
    __shared__ uint32_t Bs[128][20];
    const int n0 = blockIdx.x * 128;
    const int wid = tid >> 5, lane = tid & 31;
    const int g = lane >> 2, tig = lane & 3;

    uint32_t asm_ = (uint32_t)__cvta_generic_to_shared(&As[0][0]);
    uint32_t bsm = (uint32_t)__cvta_generic_to_shared(&Bs[0][0]);
    const uint32_t aBase = asm_ + (((wid * 16 + (lane & 15)) * 20 + ((lane >> 4) << 2)) << 2);
    const uint32_t bBase = bsm + ((((((lane >> 4) << 3) + (lane & 7)) * 20
                                   + (((lane >> 3) & 1) << 2)) << 2));

    const int lr = tid >> 2, lj = tid & 3;

    float acc[16][4];
#pragma unroll
    for (int nt = 0; nt < 16; nt++)
#pragma unroll
        for (int e = 0; e < 4; e++) acc[nt][e] = 0.f;

    float4 pa[2][2], pb[2][2];
#pragma unroll
    for (int i = 0; i < 2; i++) {
        int r = lr + i * 64, gk = lj * 8;
        pa[i][0] = *(const float4*)&A[(m0 + r) * DIMH + gk];
        pa[i][1] = *(const float4*)&A[(m0 + r) * DIMH + gk + 4];
        pb[i][0] = *(const float4*)&W[(n0 + r) * DIMH + gk];
        pb[i][1] = *(const float4*)&W[(n0 + r) * DIMH + gk + 4];
    }

    for (int kc = 0; kc < 8; kc++) {
#pragma unroll
        for (int i = 0; i < 2; i++) {
            int r = lr + i * 64;
            uint4 apk = make_uint4(packbf2(pa[i][0].x, pa[i][0].y), packbf2(pa[i][0].z, pa[i][0].w),
                                   packbf2(pa[i][1].x, pa[i][1].y), packbf2(pa[i][1].z, pa[i][1].w));
            uint4 bpk = make_uint4(packbf2(pb[i][0].x, pb[i][0].y), packbf2(pb[i][0].z, pb[i][0].w),
                                   packbf2(pb[i][1].x, pb[i][1].y), packbf2(pb[i][1].z, pb[i][1].w));
            *(uint4*)&As[r][lj * 4] = apk;
            *(uint4*)&Bs[r][lj * 4] = bpk;
        }
        __syncthreads();
        if (kc < 7) {
            int gk = (kc + 1) * 32 + lj * 8;
#pragma unroll
            for (int i = 0; i < 2; i++) {
                int r = lr + i * 64;
                pa[i][0] = *(const float4*)&A[(m0 + r) * DIMH + gk];
                pa[i][1] = *(const float4*)&A[(m0 + r) * DIMH + gk + 4];
                pb[i][0] = *(const float4*)&W[(n0 + r) * DIMH + gk];
                pb[i][1] = *(const float4*)&W[(n0 + r) * DIMH + gk + 4];
            }
        }
#pragma unroll
        for (int s = 0; s < 2; s++) {
            uint32_t a0, a1, a2, a3;
            ldmat4(a0, a1, a2, a3, aBase + s * 32);
#pragma unroll
            for (int nt2 = 0; nt2 < 8; nt2++) {
                uint32_t b0, b1, b2, b3;
                ldmat4(b0, b1, b2, b3, bBase + nt2 * 1280 + s * 32);
                mma_bf16(acc[2 * nt2], a0, a1, a2, a3, b0, b1);
                mma_bf16(acc[2 * nt2 + 1], a0, a1, a2, a3, b2, b3);
            }
        }
        __syncthreads();
    }

    // epilogue: bf16 pair stores (col pairs are adjacent)
    const int r0 = m0 + wid * 16 + g;
    uint32_t* outp = (uint32_t*)&g_QKLh[0];
#pragma unroll
    for (int nt = 0; nt < 16; nt++) {
        int c0 = n0 + nt * 8 + tig * 2;        // even, < 512
        float bv0 = bias[c0], bv1 = bias[c0 + 1];
        outp[(r0 * 512 + c0) >> 1] = packbf2(acc[nt][0] + bv0, acc[nt][1] + bv1);
        outp[((r0 + 8) * 512 + c0) >> 1] = packbf2(acc[nt][2] + bv0, acc[nt][3] + bv1);
    }
}

// ---------------- kernel B: warp-per-row layernorm (bf16 in, bf16 out) ----------------
// lane covers cols [8*lane, 8*lane+8) (Q half) and [256+8*lane, ...) (K half), uint4 loads
__global__ void __launch_bounds__(256) ln_warp(const float* __restrict__ lnw,
                                               const float* __restrict__ lnb) {
    const int row = blockIdx.x * 8 + (threadIdx.x >> 5);
    const int lane = threadIdx.x & 31;
    const uint4* xr = (const uint4*)&g_QKLh[row * 512];

    uint4 quv = xr[lane];          // cols 8l..8l+7 (Q half)
    uint4 kuv = xr[lane + 32];     // cols 256+8l..+7 (K half)
    float x512 = g_logit512[row];

    float qv[8], kv[8];
    {
        const uint32_t* qw = (const uint32_t*)&quv;
        const uint32_t* kw = (const uint32_t*)&kuv;
#pragma unroll
        for (int w = 0; w < 4; w++) {
            float2 qf = unpackbf2(qw[w]);
            float2 kf = unpackbf2(kw[w]);
            qv[2 * w] = qf.x; qv[2 * w + 1] = qf.y;
            kv[2 * w] = kf.x; kv[2 * w + 1] = kf.y;
        }
    }

    float sum = (lane == 0) ? x512 : 0.f;
    float sq  = (lane == 0) ? x512 * x512 : 0.f;
#pragma unroll
    for (int t = 0; t < 8; t++) {
        sum += qv[t] + kv[t];
        sq  += qv[t] * qv[t] + kv[t] * kv[t];
    }
#pragma unroll
    for (int o = 16; o; o >>= 1) {
        sum += __shfl_xor_sync(0xffffffffu, sum, o);
        sq  += __shfl_xor_sync(0xffffffffu, sq, o);
    }
    float mean = sum * (1.f / 513.f);
    float var  = sq * (1.f / 513.f) - mean * mean;
    float rstd = rsqrtf(var + 1e-5f);

    const int c0 = lane * 8;
    float4 wq0 = *(const float4*)&lnw[c0];
    float4 wq1 = *(const float4*)&lnw[c0 + 4];
    float4 bq0 = *(const float4*)&lnb[c0];
    float4 bq1 = *(const float4*)&lnb[c0 + 4];
    float4 wk0 = *(const float4*)&lnw[256 + c0];
    float4 wk1 = *(const float4*)&lnw[256 + c0 + 4];
    float4 bk0 = *(const float4*)&lnb[256 + c0];
    float4 bk1 = *(const float4*)&lnb[256 + c0 + 4];
    float wqa[8] = {wq0.x, wq0.y, wq0.z, wq0.w, wq1.x, wq1.y, wq1.z, wq1.w};
    float bqa[8] = {bq0.x, bq0.y, bq0.z, bq0.w, bq1.x, bq1.y, bq1.z, bq1.w};
    float wka[8] = {wk0.x, wk0.y, wk0.z, wk0.w, wk1.x, wk1.y, wk1.z, wk1.w};
    float bka[8] = {bk0.x, bk0.y, bk0.z, bk0.w, bk1.x, bk1.y, bk1.z, bk1.w};

    uint32_t qo[4], ko[4];
#pragma unroll
    for (int w = 0; w < 4; w++) {
        float q0 = (qv[2 * w] - mean) * rstd * wqa[2 * w] + bqa[2 * w];
        float q1 = (qv[2 * w + 1] - mean) * rstd * wqa[2 * w + 1] + bqa[2 * w + 1];
        float k0 = (kv[2 * w] - mean) * rstd * wka[2 * w] + bka[2 * w];
        float k1 = (kv[2 * w + 1] - mean) * rstd * wka[2 * w + 1] + bka[2 * w + 1];
        qo[w] = packbf2(q0, q1);
        ko[w] = packbf2(k0, k1);
    }
    *(uint4*)&g_Qh[row * DIMH + c0] = make_uint4(qo[0], qo[1], qo[2], qo[3]);
    *(uint4*)&g_Kh[row * DIMH + c0] = make_uint4(ko[0], ko[1], ko[2], ko[3]);
    if (lane == 0)
        g_logit[row] = (x512 - mean) * rstd * lnw[512] + lnb[512];
}

// ---------------- kernel D: causal attention partial LSE (bf16 + ldmatrix + prefetch) ----------------
__global__ void __launch_bounds__(256) attn_bf16() {
    int bx = blockIdx.x;
    int seg = bx / 36;
    int jid = bx - seg * 36;
    int rb = JOB_RB[jid];
    int ch = JOB_CH[jid];

    __shared__ uint32_t Qp[128][20];
    __shared__ uint32_t Kp[128][20];
    const int tid = threadIdx.x;
    const int wid = tid >> 5, lane = tid & 31;
    const int g = lane >> 2, tig = lane & 3;
    const int base = seg * SEGL;

    const uint32_t* Qg = (const uint32_t*)&g_Qh[0];
    const uint32_t* Kg = (const uint32_t*)&g_Kh[0];

    uint32_t qsm = (uint32_t)__cvta_generic_to_shared(&Qp[0][0]);
    uint32_t ksm = (uint32_t)__cvta_generic_to_shared(&Kp[0][0]);
    const uint32_t aBase = qsm + (((wid * 16 + (lane & 15)) * 20 + ((lane >> 4) << 2)) << 2);
    const uint32_t bBase = ksm + ((((((lane >> 4) << 3) + (lane & 7)) * 20
                                   + (((lane >> 3) & 1) << 2)) << 2));

    const int lr = tid >> 2, lj = tid & 3;

    float acc[16][4];
#pragma unroll
    for (int nt = 0; nt < 16; nt++)
#pragma unroll
        for (int e = 0; e < 4; e++) acc[nt][e] = 0.f;

    uint4 pq[2], pk[2];
#pragma unroll
    for (int i = 0; i < 2; i++) {
        int r = lr + i * 64;
        pq[i] = *(const uint4*)&Qg[(base + rb * 128 + r) * 128 + lj * 4];
        pk[i] = *(const uint4*)&Kg[(base + ch * 128 + r) * 128 + lj * 4];
    }

    for (int kc = 0; kc < 8; kc++) {
#pragma unroll
        for (int i = 0; i < 2; i++) {
            int r = lr + i * 64;
            *(uint4*)&Qp[r][lj * 4] = pq[i];
            *(uint4*)&Kp[r][lj * 4] = pk[i];
        }
        __syncthreads();
        if (kc < 7) {
            int gk = (kc + 1) * 16 + lj * 4;
#pragma unroll
            for (int i = 0; i < 2; i++) {
                int r = lr + i * 64;
                pq[i] = *(const uint4*)&Qg[(base + rb * 128 + r) * 128 + gk];
                pk[i] = *(const uint4*)&Kg[(base + ch * 128 + r) * 128 + gk];
            }
        }
#pragma unroll
        for (int s = 0; s < 2; s++) {
            uint32_t a0, a1, a2, a3;
            ldmat4(a0, a1, a2, a3, aBase + s * 32);
#pragma unroll
            for (int nt2 = 0; nt2 < 8; nt2++) {
                uint32_t b0, b1, b2, b3;
                ldmat4(b0, b1, b2, b3, bBase + nt2 * 1280 + s * 32);
                mma_bf16(acc[2 * nt2], a0, a1, a2, a3, b0, b1);
                mma_bf16(acc[2 * nt2 + 1], a0, a1, a2, a3, b2, b3);
            }
        }
        __syncthreads();
    }

    const int pbase = ((seg * 8 + rb) * 8 + ch) * 128;
    const int rin0 = wid * 16 + g;
#pragma unroll
    for (int h = 0; h < 2; h++) {
        int rin = rin0 + h * 8;
        int irow = rb * 128 + rin;
        float mx = -INFINITY;
#pragma unroll
        for (int nt = 0; nt < 16; nt++) {
#pragma unroll
            for (int e = 0; e < 2; e++) {
                int jcol = ch * 128 + nt * 8 + tig * 2 + e;
                float v = acc[nt][h * 2 + e];
                if (jcol >= irow) v = -INFINITY;
                acc[nt][h * 2 + e] = v;
                mx = fmaxf(mx, v);
            }
        }
        mx = fmaxf(mx, __shfl_xor_sync(0xffffffffu, mx, 1));
        mx = fmaxf(mx, __shfl_xor_sync(0xffffffffu, mx, 2));
        float mb = fmaxf(mx, -3.0e38f);
        float s = 0.f;
#pragma unroll
        for (int nt = 0; nt < 16; nt++) {
            s += __expf(acc[nt][h * 2 + 0] - mb);
            s += __expf(acc[nt][h * 2 + 1] - mb);
        }
        s += __shfl_xor_sync(0xffffffffu, s, 1);
        s += __shfl_xor_sync(0xffffffffu, s, 2);
        if (tig == 0) {
            g_partM[pbase + rin] = mx;
            g_partL[pbase + rin] = s;
        }
    }
}

// ---------------- kernel E: combine/zseg pre-phase + cond sum + scatter + final ----------------
__global__ void __launch_bounds__(256) cond_final(const float* __restrict__ wts,
                                                  const int* __restrict__ ii,
                                                  const int* __restrict__ jj,
                                                  float* __restrict__ out) {
    int tid = threadIdx.x;
    int bx = blockIdx.x;

    // --- pre-phase: logZ merge (blocks 0..31) and zseg (blocks 32..39) ---
    if (bx < 32) {
        int i = bx * 256 + tid;
        int seg = i >> 10;
        int r = i & 1023;
        int rb = r >> 7;
        int rr = r & 127;
        int pb = ((seg * 8 + rb) * 8) * 128 + rr;
        float m[8], l[8];
#pragma unroll
        for (int c = 0; c < 8; c++) {
            m[c] = g_partM[pb + c * 128];
            l[c] = g_partL[pb + c * 128];
        }
        float M = -INFINITY;
#pragma unroll
        for (int c = 0; c < 8; c++)
            M = fmaxf(M, (l[c] > 0.f) ? m[c] : -INFINITY);
        float Mb = fmaxf(M, -3.0e38f);
        float L = 0.f;
#pragma unroll
        for (int c = 0; c < 8; c++)
            L += l[c] * __expf(m[c] - Mb);
        g_logZ[i] = (L > 0.f) ? (M + logf(L)) : -INFINITY;
    } else if (bx < 40) {
        int seg = bx - 32;
        const float* lp = &g_logit[seg * SEGL];
        float vals[4];
        float mx = -INFINITY;
#pragma unroll
        for (int q = 0; q < 4; q++) { vals[q] = lp[tid + q * 256]; mx = fmaxf(mx, vals[q]); }
        __shared__ float shz[8];
#pragma unroll
        for (int o = 16; o; o >>= 1) mx = fmaxf(mx, __shfl_xor_sync(0xffffffffu, mx, o));
        if ((tid & 31) == 0) shz[tid >> 5] = mx;
        __syncthreads();
        float bm = -INFINITY;
#pragma unroll
        for (int i2 = 0; i2 < 8; i2++) bm = fmaxf(bm, shz[i2]);
        __syncthreads();
        float s = 0.f;
#pragma unroll
        for (int q = 0; q < 4; q++) s += expf(vals[q] - bm);
#pragma unroll
        for (int o = 16; o; o >>= 1) s += __shfl_xor_sync(0xffffffffu, s, o);
        if ((tid & 31) == 0) shz[tid >> 5] = s;
        __syncthreads();
        if (tid == 0) {
            float tot = 0.f;
#pragma unroll
            for (int i2 = 0; i2 < 8; i2++) tot += shz[i2];
            g_z[seg] = bm + logf(tot);
        }
        __syncthreads();
    }

    // --- cond gather + scatter; fp32 partial chains, x4 unroll, 4 iterations ---
    const int lane = tid & 31;
    const int warp = tid >> 5;
    const int gw = bx * 8 + warp;
    const int S = COND_GRID * 8;            // 4096 warps; 16 edges/warp; x4 unroll -> 4 iters
    const uint4* Qg = (const uint4*)&g_Qh[0];
    const uint4* Kg = (const uint4*)&g_Kh[0];
    double acc = 0.0;
    for (int e0 = gw; e0 < EPAIR; e0 += S * 4) {
        int iv[4], jv[4];
        float wv[4];
#pragma unroll
        for (int u = 0; u < 4; u++) {
            int e = e0 + u * S;
            iv[u] = ii[e];
            jv[u] = jj[e];
            wv[u] = wts[e];
        }
        uint4 qu[4], ku[4];
#pragma unroll
        for (int u = 0; u < 4; u++) {
            qu[u] = Qg[iv[u] * 32 + lane];
            ku[u] = Kg[jv[u] * 32 + lane];
        }
        float part[4];
#pragma unroll
        for (int u = 0; u < 4; u++) {
            const uint32_t* qw = (const uint32_t*)&qu[u];
            const uint32_t* kw = (const uint32_t*)&ku[u];
            float d = 0.f;
#pragma unroll
            for (int w = 0; w < 4; w++) {
                float2 qf = unpackbf2(qw[w]);
                float2 kf = unpackbf2(kw[w]);
                d += qf.x * kf.x + qf.y * kf.y;
            }
            part[u] = wv[u] * d;
            if (lane == 0) atomicAdd(&g_Wall[iv[u]], wv[u]);
        }
        acc += (double)((part[0] + part[1]) + (part[2] + part[3]));
    }
    __shared__ double shd[256];
    shd[tid] = acc;
    __syncthreads();
    for (int s = 128; s; s >>= 1) {
        if (tid < s) shd[tid] += shd[tid + s];
        __syncthreads();
    }
    __shared__ bool is_last;
    if (tid == 0) {
        atomicAdd(&g_accCond, shd[0]);
        __threadfence();
        unsigned old = atomicInc(&g_ctr, COND_GRID - 1);
        is_last = (old == COND_GRID - 1);
    }
    __syncthreads();
    if (is_last) {
        __threadfence();
        double facc = 0.0;
        for (int i = tid; i < N_TOK; i += 256) {
            float w = g_Wall[i];
            if (w > 0.f) {
                int seg = i >> 10;
                facc += (double)w * ((double)g_logit[i] - (double)g_z[seg] - (double)g_logZ[i]);
            }
        }
        __syncthreads();
        shd[tid] = facc;
        __syncthreads();
        for (int s = 128; s; s >>= 1) {
            if (tid < s) shd[tid] += shd[tid + s];
            __syncthreads();
        }
        if (tid == 0) {
            double cond = atomicAdd(&g_accCond, 0.0);
            out[0] = -(float)(cond + shd[0]);
        }
    }
}

// ---------------- launch ----------------
extern "C" void kernel_launch(void* const* d_in, const int* in_sizes, int n_in,
                              void* d_out, int out_size) {
    const float* hidden = (const float*)d_in[0];
    const float* Wp     = (const float*)d_in[1];
    const float* bp     = (const float*)d_in[2];
    const float* lnw    = (const float*)d_in[3];
    const float* lnb    = (const float*)d_in[4];
    const float* wts    = (const float*)d_in[5];
    const int*   ii     = (const int*)d_in[6];
    const int*   jj     = (const int*)d_in[7];
    float* out = (float*)d_out;

    proj_bf16<<<dim3(5, 64), 256>>>(hidden, Wp, bp);
    ln_warp<<<1024, 256>>>(lnw, lnb);
    attn_bf16<<<288, 256>>>();
    cond_final<<<COND_GRID, 256>>>(wts, ii, jj, out);
}